// round 3
// baseline (speedup 1.0000x reference)
#include <cuda_runtime.h>
#include <cstdint>

// B=16384, N=64, D=64, O=64
// softmax(others@a2 + robot@a1) == softmax(others@a2)   (robot term constant)
// out = elu( (diag(1,attn) .* h) @ W )
// Single fused kernel. W MMA B-fragments live in REGISTERS (32/lane, loaded
// once). v2 = W@a2 computed per-CTA. h double-buffered via cp.async.
// Warp w computes all 64 rows x cols [16w,16w+16) (4 m-tiles x 2 n-tiles).

#define GB 8      // batches per CTA
#define HS 68     // h smem row stride (floats)

__device__ __forceinline__ unsigned f2tf32(float x) {
    unsigned r;
    asm("cvt.rna.tf32.f32 %0, %1;" : "=r"(r) : "f"(x));
    return r;
}

__device__ __forceinline__ float elu1(float x) {
    return x > 0.f ? x : expm1f(x);
}

__device__ __forceinline__ void cp_async16(uint32_t saddr, const void* gptr) {
    asm volatile("cp.async.cg.shared.global [%0], [%1], 16;\n"
                 :: "r"(saddr), "l"(gptr));
}

__global__ __launch_bounds__(128, 5)
void gat_fused_kernel(const float* __restrict__ h,
                      const float* __restrict__ W,
                      const float* __restrict__ a,
                      float* __restrict__ out) {
    __shared__ float sh[2][64 * HS];   // double-buffered h (fp32)
    __shared__ float sdots[64];
    __shared__ float sfac[64];
    __shared__ float sv2[64];

    const int tid  = threadIdx.x;
    const int lane = tid & 31;
    const int warp = tid >> 5;
    const int gid  = lane >> 2;   // 0..7
    const int tig  = lane & 3;    // 0..3

    // ---- W B-fragments into registers (once). warp w: cols [16w, 16w+16) ----
    // bfr[kk][nt][j]: b0=W[kk*8+tig][16w+nt*8+gid], b1=W[kk*8+tig+4][same col]
    unsigned bfr[8][2][2];
    {
        const int n0 = warp * 16 + gid;
#pragma unroll
        for (int kk = 0; kk < 8; ++kk)
#pragma unroll
            for (int nt = 0; nt < 2; ++nt) {
                int col = n0 + nt * 8;
                bfr[kk][nt][0] = f2tf32(W[(kk * 8 + tig) * 64 + col]);
                bfr[kk][nt][1] = f2tf32(W[(kk * 8 + tig + 4) * 64 + col]);
            }
    }

    // ---- v2 = W @ a2 (per CTA; threads 0..63) ----
    if (tid < 64) {
        const float* a2 = a + 64;
        float s = 0.f;
#pragma unroll
        for (int o = 0; o < 64; ++o) s = fmaf(W[tid * 64 + o], a2[o], s);
        sv2[tid] = s;
    }

    const size_t base = (size_t)blockIdx.x * GB * 4096;

    // ---- prefetch batch 0 ----
    {
        const float* hb = h + base;
        uint32_t sb = (uint32_t)__cvta_generic_to_shared(&sh[0][0]);
#pragma unroll
        for (int c = tid; c < 1024; c += 128) {
            int row = c >> 4, q = c & 15;
            cp_async16(sb + (row * HS + q * 4) * 4, hb + c * 4);
        }
        asm volatile("cp.async.commit_group;\n");
    }

    for (int g = 0; g < GB; ++g) {
        const int buf = g & 1;

        asm volatile("cp.async.wait_group 0;\n");
        __syncthreads();   // h[g] visible; prev iter fully done; sv2 ready

        // ---- prefetch batch g+1 ----
        if (g + 1 < GB) {
            const float* hb = h + base + (size_t)(g + 1) * 4096;
            uint32_t sb = (uint32_t)__cvta_generic_to_shared(&sh[buf ^ 1][0]);
#pragma unroll
            for (int c = tid; c < 1024; c += 128) {
                int row = c >> 4, q = c & 15;
                cp_async16(sb + (row * HS + q * 4) * 4, hb + c * 4);
            }
            asm volatile("cp.async.commit_group;\n");
        }

        // ---- dots[n] = h[n]·v2 : one thread per row (conflict-free) ----
        if (tid < 64) {
            const float4* hp = reinterpret_cast<const float4*>(&sh[buf][tid * HS]);
            const float4* vp = reinterpret_cast<const float4*>(sv2);
            float s = 0.f;
#pragma unroll
            for (int k = 0; k < 16; ++k) {
                float4 hv = hp[k];
                float4 vv = vp[k];
                s = fmaf(hv.x, vv.x, s);
                s = fmaf(hv.y, vv.y, s);
                s = fmaf(hv.z, vv.z, s);
                s = fmaf(hv.w, vv.w, s);
            }
            sdots[tid] = s;
        }
        __syncthreads();

        // ---- softmax over scores 1..63 (warp 0) -> sfac ----
        if (warp == 0) {
            float x0 = (lane >= 1) ? sdots[lane] : -1e30f;
            float x1 = sdots[lane + 32];
            float m = fmaxf(x0, x1);
#pragma unroll
            for (int off = 16; off; off >>= 1)
                m = fmaxf(m, __shfl_xor_sync(0xffffffffu, m, off));
            float e0 = (lane >= 1) ? expf(x0 - m) : 0.f;
            float e1 = expf(x1 - m);
            float s = e0 + e1;
#pragma unroll
            for (int off = 16; off; off >>= 1)
                s += __shfl_xor_sync(0xffffffffu, s, off);
            float inv = 1.f / s;
            if (lane >= 1) sfac[lane] = e0 * inv;
            sfac[lane + 32] = e1 * inv;
            if (lane == 0) sfac[0] = 1.f;   // robot row unscaled
        }
        __syncthreads();

        // ---- GEMM: warp w -> all rows x cols [16w,16w+16) ----
        float acc[4][2][4];
#pragma unroll
        for (int mt = 0; mt < 4; ++mt)
#pragma unroll
            for (int nt = 0; nt < 2; ++nt)
#pragma unroll
                for (int k = 0; k < 4; ++k) acc[mt][nt][k] = 0.f;

        const float* shb = &sh[buf][0];
#pragma unroll
        for (int mt = 0; mt < 4; ++mt) {
            const int r0 = mt * 16 + gid;
            const float fA = sfac[r0];
            const float fB = sfac[r0 + 8];
#pragma unroll
            for (int kk = 0; kk < 8; ++kk) {
                const int c = kk * 8 + tig;
                unsigned a0 = f2tf32(shb[r0 * HS + c] * fA);
                unsigned a1 = f2tf32(shb[(r0 + 8) * HS + c] * fB);
                unsigned a2 = f2tf32(shb[r0 * HS + c + 4] * fA);
                unsigned a3 = f2tf32(shb[(r0 + 8) * HS + c + 4] * fB);
#pragma unroll
                for (int nt = 0; nt < 2; ++nt) {
                    asm volatile(
                        "mma.sync.aligned.m16n8k8.row.col.f32.tf32.tf32.f32 "
                        "{%0,%1,%2,%3}, {%4,%5,%6,%7}, {%8,%9}, {%0,%1,%2,%3};"
                        : "+f"(acc[mt][nt][0]), "+f"(acc[mt][nt][1]),
                          "+f"(acc[mt][nt][2]), "+f"(acc[mt][nt][3])
                        : "r"(a0), "r"(a1), "r"(a2), "r"(a3),
                          "r"(bfr[kk][nt][0]), "r"(bfr[kk][nt][1]));
                }
            }
        }

        // ---- epilogue: elu + store ----
        float* ob = out + base + (size_t)g * 4096;
#pragma unroll
        for (int mt = 0; mt < 4; ++mt) {
            const int rA = mt * 16 + gid;
            const int rB = rA + 8;
#pragma unroll
            for (int nt = 0; nt < 2; ++nt) {
                int col = warp * 16 + nt * 8 + tig * 2;
                float2 v0 = make_float2(elu1(acc[mt][nt][0]), elu1(acc[mt][nt][1]));
                float2 v1 = make_float2(elu1(acc[mt][nt][2]), elu1(acc[mt][nt][3]));
                *reinterpret_cast<float2*>(ob + rA * 64 + col) = v0;
                *reinterpret_cast<float2*>(ob + rB * 64 + col) = v1;
            }
        }
    }
}

extern "C" void kernel_launch(void* const* d_in, const int* in_sizes, int n_in,
                              void* d_out, int out_size) {
    const float* h = (const float*)d_in[0];   // (16384, 64, 64) f32
    const float* W = (const float*)d_in[1];   // (64, 64) f32
    const float* a = (const float*)d_in[2];   // (128, 1) f32
    float* out = (float*)d_out;               // (16384, 64, 64) f32

    gat_fused_kernel<<<16384 / GB, 128>>>(h, W, a, out);
}